// round 9
// baseline (speedup 1.0000x reference)
#include <cuda_runtime.h>
#include <cuda_fp16.h>
#include <cstdint>

// ---------------- problem constants ----------------
#define NN     50000
#define FDIM   128
#define EMAX   600000

// ---------------- device scratch ----------------
__device__ __half   g_t[(size_t)NN * FDIM];   // GEMM out (pre-aggregation), fp16
__device__ __half   g_xh[(size_t)NN * FDIM];  // fp16 activations (ping)
__device__ __half   g_hb[(size_t)NN * FDIM];  // fp16 activations (pong)
__device__ uint32_t g_Bp[3][8192];            // lane-packed fp16 W fragments
__device__ int      g_cnt[NN];                // self-zeroed by k_scan
__device__ int      g_cur[NN];                // scatter cursors (init = rowptr)
__device__ int      g_rowptr[NN + 1];
__device__ int      g_bsums[64];
__device__ int      g_bflag[64];              // zeroed by k_count each call
__device__ float    g_dinv[NN];
__device__ int2     g_edge[EMAX];             // {src, __float_as_int(norm)}

// ---------------- setup kernels ----------------
__global__ void k_count(const int* __restrict__ ei, int E) {
    int e = blockIdx.x * blockDim.x + threadIdx.x;
    if (e < 64) g_bflag[e] = 0;               // reset lookback flags for this call
    if (e < E) atomicAdd(&g_cnt[ei[E + e]], 1);   // dst = row 1
}

// single-pass scan: block scan + flag-published block sums + parallel lookback.
// Also: dinv, self-zero of cnt, cursor init. 49 blocks, all co-resident.
__global__ __launch_bounds__(1024) void k_scan(int n, int E) {
    __shared__ int s[1024];
    __shared__ int sred[64];
    __shared__ int pre_sh;
    const int tid = threadIdx.x;
    const int bid = blockIdx.x;
    int i = bid * 1024 + tid;
    int v = (i < n) ? g_cnt[i] : 0;
    if (i < n) {
        g_dinv[i] = rsqrtf((float)(v + 1));   // +1 self loop
        g_cnt[i] = 0;                          // ready for next call
    }
    s[tid] = v;
    __syncthreads();
    for (int off = 1; off < 1024; off <<= 1) {
        int t = (tid >= off) ? s[tid - off] : 0;
        __syncthreads();
        s[tid] += t;
        __syncthreads();
    }
    // publish inclusive block total
    if (tid == 1023) {
        g_bsums[bid] = s[1023];
        __threadfence();
        atomicExch(&g_bflag[bid], 1);
    }
    // lookback: sum totals of all predecessor blocks
    if (tid < 64) {
        int val = 0;
        if (tid < bid) {
            while (atomicAdd(&g_bflag[tid], 0) == 0) { }
            val = atomicAdd(&g_bsums[tid], 0);
        }
        sred[tid] = val;
    }
    __syncthreads();
    if (tid < 32) {
        int v2 = sred[tid] + sred[tid + 32];
#pragma unroll
        for (int o = 16; o; o >>= 1) v2 += __shfl_down_sync(0xffffffffu, v2, o);
        if (tid == 0) pre_sh = v2;
    }
    __syncthreads();
    int base = pre_sh + s[tid] - v;           // exclusive prefix
    if (i < n) {
        g_rowptr[i] = base;
        g_cur[i] = base;                       // scatter cursor
    }
    if (i == 0) g_rowptr[n] = E;
}

__global__ void k_scatter(const int* __restrict__ ei, int E) {
    int e = blockIdx.x * blockDim.x + threadIdx.x;
    if (e >= E) return;
    int s = ei[e];
    int d = ei[E + e];
    int pos = atomicAdd(&g_cur[d], 1);
    g_edge[pos] = make_int2(s, __float_as_int(g_dinv[s] * g_dinv[d]));
}

// pre-permute all 3 weight matrices into lane-packed fp16 m16n8k16 B fragments
__global__ __launch_bounds__(256) void k_bperm3(const float* __restrict__ W1,
                                                const float* __restrict__ W2,
                                                const float* __restrict__ W3) {
    int l = blockIdx.x >> 4;                   // 16 blocks per layer
    const float* W = (l == 0) ? W1 : (l == 1) ? W2 : W3;
    uint2* Bp = (uint2*)g_Bp[l];
    int slot = (blockIdx.x & 15) * 256 + threadIdx.x;   // 4096 slots/layer
    int lane = slot & 31;
    int group = slot >> 5;                     // 128 groups
    int nt = group >> 3, kt = group & 7;
    int g = lane >> 2, tg = lane & 3;
    int n = nt * 8 + g;
    int k0 = kt * 16 + tg * 2;
    __half2 lo = __floats2half2_rn(W[k0 * 128 + n],       W[(k0 + 1) * 128 + n]);
    __half2 hi = __floats2half2_rn(W[(k0 + 8) * 128 + n], W[(k0 + 9) * 128 + n]);
    uint2 v;
    v.x = *(uint32_t*)&lo;
    v.y = *(uint32_t*)&hi;
    Bp[slot] = v;
}

// x (fp32) -> fp16
__global__ void k_x2h(const float* __restrict__ x, __half* __restrict__ xh, int n2) {
    int i = blockIdx.x * blockDim.x + threadIdx.x;
    if (i < n2) {
        float2 v = ((const float2*)x)[i];
        ((__half2*)xh)[i] = __floats2half2_rn(v.x, v.y);
    }
}

// ---------------- fp16 mma.sync GEMM: C = A @ W (fp16 in/out, fp32 acc) ----------------
#define HPITCH 136                                  // halves per smem row
#define SMEM_GEMM (128 * HPITCH * 2)                // 34816 B

__device__ __forceinline__ void mma_f16(float* c, const uint32_t* a, const uint32_t* b) {
    asm volatile(
        "mma.sync.aligned.m16n8k16.row.col.f32.f16.f16.f32 "
        "{%0,%1,%2,%3}, {%4,%5,%6,%7}, {%8,%9}, {%0,%1,%2,%3};"
        : "+f"(c[0]), "+f"(c[1]), "+f"(c[2]), "+f"(c[3])
        : "r"(a[0]), "r"(a[1]), "r"(a[2]), "r"(a[3]), "r"(b[0]), "r"(b[1]));
}

__global__ __launch_bounds__(256) void k_gemm_h(const __half* __restrict__ A,
                                                const uint2* __restrict__ Bp,
                                                __half* __restrict__ C, int nrows) {
    extern __shared__ __half smh[];                 // [128][136] fp16

    const int tid  = threadIdx.x;
    const int lane = tid & 31;
    const int wid  = tid >> 5;
    const int row0 = blockIdx.x * 128;

    // stage A tile: raw fp16 copy, coalesced (2048 uint4, 8/thread)
#pragma unroll
    for (int i = 0; i < 8; i++) {
        int idx = i * 256 + tid;
        int r = idx >> 4;
        int c = idx & 15;
        uint4 v = make_uint4(0u, 0u, 0u, 0u);
        if (row0 + r < nrows)
            v = ((const uint4*)(A + (size_t)(row0 + r) * 128))[c];
        *(uint4*)(smh + r * HPITCH + c * 8) = v;
    }
    __syncthreads();

    const int wrow = wid >> 1;
    const int wcol = wid & 1;
    const int g = lane >> 2, tg = lane & 3;

    float acc[2][8][4];
#pragma unroll
    for (int i = 0; i < 2; i++)
#pragma unroll
        for (int j = 0; j < 8; j++)
#pragma unroll
            for (int q = 0; q < 4; q++) acc[i][j][q] = 0.f;

    const uint2* BpW = Bp + (size_t)(wcol * 8) * 8 * 32 + lane;

#pragma unroll
    for (int kt = 0; kt < 8; kt++) {
        uint2 bf[8];
#pragma unroll
        for (int j = 0; j < 8; j++)
            bf[j] = BpW[(size_t)(j * 8 + kt) * 32];
        uint32_t af[2][4];
#pragma unroll
        for (int i = 0; i < 2; i++) {
            int r = wrow * 32 + i * 16 + g;
            int c = kt * 16 + tg * 2;
            af[i][0] = *(const uint32_t*)(smh + r * HPITCH + c);
            af[i][1] = *(const uint32_t*)(smh + (r + 8) * HPITCH + c);
            af[i][2] = *(const uint32_t*)(smh + r * HPITCH + c + 8);
            af[i][3] = *(const uint32_t*)(smh + (r + 8) * HPITCH + c + 8);
        }
#pragma unroll
        for (int i = 0; i < 2; i++)
#pragma unroll
            for (int j = 0; j < 8; j++)
                mma_f16(acc[i][j], af[i], (const uint32_t*)&bf[j]);
    }

    // epilogue: half2 stores
#pragma unroll
    for (int i = 0; i < 2; i++) {
        int r = row0 + wrow * 32 + i * 16 + g;
#pragma unroll
        for (int j = 0; j < 8; j++) {
            int col = wcol * 64 + j * 8 + tg * 2;
            if (r < nrows)
                *(__half2*)(C + (size_t)r * 128 + col) =
                    __floats2half2_rn(acc[i][j][0], acc[i][j][1]);
            if (r + 8 < nrows)
                *(__half2*)(C + (size_t)(r + 8) * 128 + col) =
                    __floats2half2_rn(acc[i][j][2], acc[i][j][3]);
        }
    }
}

// ---------------- aggregation: half-warp per node, uint4 gathers, 8-edge unroll ----------------
__device__ __forceinline__ void accum8(float4& A, float4& B, uint4 r, float m) {
    float2 p0 = __half22float2(*(__half2*)&r.x);
    float2 p1 = __half22float2(*(__half2*)&r.y);
    float2 p2 = __half22float2(*(__half2*)&r.z);
    float2 p3 = __half22float2(*(__half2*)&r.w);
    A.x = fmaf(p0.x, m, A.x); A.y = fmaf(p0.y, m, A.y);
    A.z = fmaf(p1.x, m, A.z); A.w = fmaf(p1.y, m, A.w);
    B.x = fmaf(p2.x, m, B.x); B.y = fmaf(p2.y, m, B.y);
    B.z = fmaf(p3.x, m, B.z); B.w = fmaf(p3.y, m, B.w);
}

__global__ __launch_bounds__(128) void k_aggregate(const __half* __restrict__ H,
                                                   const float* __restrict__ bias,
                                                   __half* __restrict__ Hout,
                                                   float* __restrict__ Fout,
                                                   float* __restrict__ Fout2,
                                                   int n, int relu) {
    const int tid = threadIdx.x;
    const int hw = (tid >> 4) & 1;          // half-warp within warp
    const int hl = tid & 15;                // lane within half-warp
    const int node = blockIdx.x * 8 + (tid >> 5) * 2 + hw;
    if (node >= n) return;

    const uint4* H4 = (const uint4*)H;      // 16 uint4 per 128-half row

    float di = g_dinv[node];
    float di2 = di * di;
    uint4 sr = __ldcg(H4 + (size_t)node * 16 + hl);
    float4 a0 = make_float4(0.f, 0.f, 0.f, 0.f), a1 = a0, a2 = a0, a3 = a0;
    accum8(a0, a1, sr, di2);

    int e = g_rowptr[node], e1 = g_rowptr[node + 1];
    for (; e + 7 < e1; e += 8) {
        int2 E0 = g_edge[e],     E1 = g_edge[e + 1];
        int2 E2 = g_edge[e + 2], E3 = g_edge[e + 3];
        int2 E4 = g_edge[e + 4], E5 = g_edge[e + 5];
        int2 E6 = g_edge[e + 6], E7 = g_edge[e + 7];
        uint4 r0 = __ldcg(H4 + (size_t)E0.x * 16 + hl);
        uint4 r1 = __ldcg(H4 + (size_t)E1.x * 16 + hl);
        uint4 r2 = __ldcg(H4 + (size_t)E2.x * 16 + hl);
        uint4 r3 = __ldcg(H4 + (size_t)E3.x * 16 + hl);
        uint4 r4 = __ldcg(H4 + (size_t)E4.x * 16 + hl);
        uint4 r5 = __ldcg(H4 + (size_t)E5.x * 16 + hl);
        uint4 r6 = __ldcg(H4 + (size_t)E6.x * 16 + hl);
        uint4 r7 = __ldcg(H4 + (size_t)E7.x * 16 + hl);
        accum8(a0, a1, r0, __int_as_float(E0.y));
        accum8(a2, a3, r1, __int_as_float(E1.y));
        accum8(a0, a1, r2, __int_as_float(E2.y));
        accum8(a2, a3, r3, __int_as_float(E3.y));
        accum8(a0, a1, r4, __int_as_float(E4.y));
        accum8(a2, a3, r5, __int_as_float(E5.y));
        accum8(a0, a1, r6, __int_as_float(E6.y));
        accum8(a2, a3, r7, __int_as_float(E7.y));
    }
    if (e + 3 < e1) {
        int2 E0 = g_edge[e],     E1 = g_edge[e + 1];
        int2 E2 = g_edge[e + 2], E3 = g_edge[e + 3];
        uint4 r0 = __ldcg(H4 + (size_t)E0.x * 16 + hl);
        uint4 r1 = __ldcg(H4 + (size_t)E1.x * 16 + hl);
        uint4 r2 = __ldcg(H4 + (size_t)E2.x * 16 + hl);
        uint4 r3 = __ldcg(H4 + (size_t)E3.x * 16 + hl);
        accum8(a0, a1, r0, __int_as_float(E0.y));
        accum8(a2, a3, r1, __int_as_float(E1.y));
        accum8(a0, a1, r2, __int_as_float(E2.y));
        accum8(a2, a3, r3, __int_as_float(E3.y));
        e += 4;
    }
    if (e + 1 < e1) {
        int2 E0 = g_edge[e], E1 = g_edge[e + 1];
        uint4 r0 = __ldcg(H4 + (size_t)E0.x * 16 + hl);
        uint4 r1 = __ldcg(H4 + (size_t)E1.x * 16 + hl);
        accum8(a0, a1, r0, __int_as_float(E0.y));
        accum8(a2, a3, r1, __int_as_float(E1.y));
        e += 2;
    }
    if (e < e1) {
        int2 E0 = g_edge[e];
        uint4 r0 = __ldcg(H4 + (size_t)E0.x * 16 + hl);
        accum8(a0, a1, r0, __int_as_float(E0.y));
    }

    float4 b0 = *(const float4*)(bias + hl * 8);
    float4 b1 = *(const float4*)(bias + hl * 8 + 4);
    float4 o0 = make_float4(a0.x + a2.x + b0.x, a0.y + a2.y + b0.y,
                            a0.z + a2.z + b0.z, a0.w + a2.w + b0.w);
    float4 o1 = make_float4(a1.x + a3.x + b1.x, a1.y + a3.y + b1.y,
                            a1.z + a3.z + b1.z, a1.w + a3.w + b1.w);
    if (relu) {
        o0.x = fmaxf(o0.x, 0.f); o0.y = fmaxf(o0.y, 0.f);
        o0.z = fmaxf(o0.z, 0.f); o0.w = fmaxf(o0.w, 0.f);
        o1.x = fmaxf(o1.x, 0.f); o1.y = fmaxf(o1.y, 0.f);
        o1.z = fmaxf(o1.z, 0.f); o1.w = fmaxf(o1.w, 0.f);
    }
    if (Hout) {
        __half2 h0 = __floats2half2_rn(o0.x, o0.y);
        __half2 h1 = __floats2half2_rn(o0.z, o0.w);
        __half2 h2 = __floats2half2_rn(o1.x, o1.y);
        __half2 h3 = __floats2half2_rn(o1.z, o1.w);
        uint4 st;
        st.x = *(uint32_t*)&h0; st.y = *(uint32_t*)&h1;
        st.z = *(uint32_t*)&h2; st.w = *(uint32_t*)&h3;
        ((uint4*)(Hout + (size_t)node * 128))[hl] = st;
    } else {
        size_t off = (size_t)node * 128 + hl * 8;
        *(float4*)(Fout + off)     = o0;
        *(float4*)(Fout + off + 4) = o1;
        if (Fout2) {
            *(float4*)(Fout2 + off)     = o0;
            *(float4*)(Fout2 + off + 4) = o1;
        }
    }
}

// ---------------- launch ----------------
extern "C" void kernel_launch(void* const* d_in, const int* in_sizes, int n_in,
                              void* d_out, int out_size) {
    const float* x  = (const float*)d_in[0];
    const int*   ei = (const int*)d_in[1];
    const float* W1 = (const float*)d_in[2];
    const float* b1 = (const float*)d_in[3];
    const float* W2 = (const float*)d_in[4];
    const float* b2 = (const float*)d_in[5];
    const float* W3 = (const float*)d_in[6];
    const float* b3 = (const float*)d_in[7];

    int N = in_sizes[0] / FDIM;
    if (N > NN) N = NN;
    int E = in_sizes[1] / 2;
    if (E > EMAX) E = EMAX;

    static __half* t  = nullptr;
    static __half* xh = nullptr;
    static __half* hb = nullptr;
    static uint32_t* bp = nullptr;
    static cudaStream_t s2 = nullptr;
    static cudaEvent_t evF = nullptr, evJ = nullptr;
    static bool inited = false;
    if (!inited) {
        cudaGetSymbolAddress((void**)&t, g_t);
        cudaGetSymbolAddress((void**)&xh, g_xh);
        cudaGetSymbolAddress((void**)&hb, g_hb);
        cudaGetSymbolAddress((void**)&bp, g_Bp);
        cudaFuncSetAttribute(k_gemm_h, cudaFuncAttributeMaxDynamicSharedMemorySize,
                             SMEM_GEMM);
        cudaStreamCreateWithFlags(&s2, cudaStreamNonBlocking);
        cudaEventCreateWithFlags(&evF, cudaEventDisableTiming);
        cudaEventCreateWithFlags(&evJ, cudaEventDisableTiming);
        inited = true;
    }
    const uint2* Bp1 = (const uint2*)bp;
    const uint2* Bp2 = (const uint2*)(bp + 8192);
    const uint2* Bp3 = (const uint2*)(bp + 2 * 8192);

    const int nScan = (N + 1023) / 1024;
    const int n2 = N * 64;   // half2 count
    const int gGemm = (N + 127) / 128;
    const int gAgg  = (N + 7) / 8;
    float* out = (float*)d_out;
    int half = N * FDIM;
    float* out2 = (out_size >= 2 * half) ? out + half : nullptr;

    // fork: CSR build on s2, concurrent with weight/x prep + layer-1 GEMM
    cudaEventRecord(evF, 0);
    cudaStreamWaitEvent(s2, evF, 0);
    k_count<<<(E + 255) / 256, 256, 0, s2>>>(ei, E);
    k_scan<<<nScan, 1024, 0, s2>>>(N, E);
    k_scatter<<<(E + 255) / 256, 256, 0, s2>>>(ei, E);
    cudaEventRecord(evJ, s2);

    k_bperm3<<<48, 256>>>(W1, W2, W3);
    k_x2h<<<(n2 + 255) / 256, 256>>>(x, xh, n2);
    k_gemm_h<<<gGemm, 256, SMEM_GEMM>>>(xh, Bp1, t, N);

    // join: aggregation needs the CSR
    cudaStreamWaitEvent(0, evJ, 0);
    k_aggregate<<<gAgg, 128>>>(t, b1, hb, nullptr, nullptr, N, 1);
    k_gemm_h<<<gGemm, 256, SMEM_GEMM>>>(hb, Bp2, t, N);
    k_aggregate<<<gAgg, 128>>>(t, b2, xh, nullptr, nullptr, N, 1);
    k_gemm_h<<<gGemm, 256, SMEM_GEMM>>>(xh, Bp3, t, N);
    k_aggregate<<<gAgg, 128>>>(t, b3, nullptr, out, out2, N, 0);
}

// round 11
// speedup vs baseline: 1.0387x; 1.0387x over previous
#include <cuda_runtime.h>
#include <cuda_fp16.h>
#include <cstdint>

// ---------------- problem constants ----------------
#define NN     50000
#define FDIM   128
#define EMAX   600000

// ---------------- device scratch ----------------
__device__ __half   g_t[(size_t)NN * FDIM];   // GEMM out (pre-aggregation), fp16
__device__ __half   g_xh[(size_t)NN * FDIM];  // fp16 activations (ping)
__device__ __half   g_hb[(size_t)NN * FDIM];  // fp16 activations (pong)
__device__ uint32_t g_Bp[3][8192];            // lane-packed fp16 W fragments
__device__ int      g_cnt[NN];                // self-zeroed by k_scan
__device__ int      g_cur[NN];                // scatter cursors (init = rowptr)
__device__ int      g_rowptr[NN + 1];
__device__ int      g_bsums[64];
__device__ int      g_bflag[64];              // reset by k_count each call
__device__ float    g_dinv[NN];
__device__ int2     g_edge[EMAX];             // {src, __float_as_int(norm)}

// ---------------- setup kernels ----------------
// 4 independent edges per thread (4 concurrent atomic chains).
// GUARD: threads with i >= T must not run the edge loop (grid padding would
// alias edge i with edge (i-T)+T and double-process it).
__global__ void k_count(const int* __restrict__ ei, int E, int T) {
    int i = blockIdx.x * blockDim.x + threadIdx.x;
    if (i < 64) g_bflag[i] = 0;               // reset lookback flags (i<64 < T always)
    if (i >= T) return;
#pragma unroll
    for (int k = 0; k < 4; k++) {
        int e = i + k * T;
        if (e < E) atomicAdd(&g_cnt[ei[E + e]], 1);   // dst = row 1
    }
}

// single-pass scan: block scan + flag-published block sums + parallel lookback.
// Also: dinv, self-zero of cnt, cursor init. 49 blocks, all co-resident.
__global__ __launch_bounds__(1024) void k_scan(int n, int E) {
    __shared__ int s[1024];
    __shared__ int sred[64];
    __shared__ int pre_sh;
    const int tid = threadIdx.x;
    const int bid = blockIdx.x;
    int i = bid * 1024 + tid;
    int v = (i < n) ? g_cnt[i] : 0;
    if (i < n) {
        g_dinv[i] = rsqrtf((float)(v + 1));   // +1 self loop
        g_cnt[i] = 0;                          // ready for next call
    }
    s[tid] = v;
    __syncthreads();
    for (int off = 1; off < 1024; off <<= 1) {
        int t = (tid >= off) ? s[tid - off] : 0;
        __syncthreads();
        s[tid] += t;
        __syncthreads();
    }
    if (tid == 1023) {
        g_bsums[bid] = s[1023];
        __threadfence();
        atomicExch(&g_bflag[bid], 1);
    }
    if (tid < 64) {
        int val = 0;
        if (tid < bid) {
            while (atomicAdd(&g_bflag[tid], 0) == 0) { }
            val = atomicAdd(&g_bsums[tid], 0);
        }
        sred[tid] = val;
    }
    __syncthreads();
    if (tid < 32) {
        int v2 = sred[tid] + sred[tid + 32];
#pragma unroll
        for (int o = 16; o; o >>= 1) v2 += __shfl_down_sync(0xffffffffu, v2, o);
        if (tid == 0) pre_sh = v2;
    }
    __syncthreads();
    int base = pre_sh + s[tid] - v;
    if (i < n) {
        g_rowptr[i] = base;
        g_cur[i] = base;
    }
    if (i == 0) g_rowptr[n] = E;
}

// 4 independent edges per thread (same padding guard)
__global__ void k_scatter(const int* __restrict__ ei, int E, int T) {
    int i = blockIdx.x * blockDim.x + threadIdx.x;
    if (i >= T) return;
#pragma unroll
    for (int k = 0; k < 4; k++) {
        int e = i + k * T;
        if (e < E) {
            int s = ei[e];
            int d = ei[E + e];
            int pos = atomicAdd(&g_cur[d], 1);
            g_edge[pos] = make_int2(s, __float_as_int(g_dinv[s] * g_dinv[d]));
        }
    }
}

// pre-permute all 3 weight matrices into lane-packed fp16 m16n8k16 B fragments
__global__ __launch_bounds__(256) void k_bperm3(const float* __restrict__ W1,
                                                const float* __restrict__ W2,
                                                const float* __restrict__ W3) {
    int l = blockIdx.x >> 4;                   // 16 blocks per layer
    const float* W = (l == 0) ? W1 : (l == 1) ? W2 : W3;
    uint2* Bp = (uint2*)g_Bp[l];
    int slot = (blockIdx.x & 15) * 256 + threadIdx.x;   // 4096 slots/layer
    int lane = slot & 31;
    int group = slot >> 5;                     // 128 groups
    int nt = group >> 3, kt = group & 7;
    int g = lane >> 2, tg = lane & 3;
    int n = nt * 8 + g;
    int k0 = kt * 16 + tg * 2;
    __half2 lo = __floats2half2_rn(W[k0 * 128 + n],       W[(k0 + 1) * 128 + n]);
    __half2 hi = __floats2half2_rn(W[(k0 + 8) * 128 + n], W[(k0 + 9) * 128 + n]);
    uint2 v;
    v.x = *(uint32_t*)&lo;
    v.y = *(uint32_t*)&hi;
    Bp[slot] = v;
}

// ---------------- fp16 mma.sync GEMM (fp16 or fp32 input, fp16 out, fp32 acc) ----------------
#define HPITCH 136                                  // halves per smem row
#define SMEM_GEMM (128 * HPITCH * 2)                // 34816 B

__device__ __forceinline__ void mma_f16(float* c, const uint32_t* a, const uint32_t* b) {
    asm volatile(
        "mma.sync.aligned.m16n8k16.row.col.f32.f16.f16.f32 "
        "{%0,%1,%2,%3}, {%4,%5,%6,%7}, {%8,%9}, {%0,%1,%2,%3};"
        : "+f"(c[0]), "+f"(c[1]), "+f"(c[2]), "+f"(c[3])
        : "r"(a[0]), "r"(a[1]), "r"(a[2]), "r"(a[3]), "r"(b[0]), "r"(b[1]));
}

// shared body: after A tile is staged in smem, run mainloop + epilogue
__device__ __forceinline__ void gemm_body(__half* smh, const uint2* __restrict__ Bp,
                                          __half* __restrict__ C, int nrows, int row0,
                                          int tid) {
    const int lane = tid & 31;
    const int wid  = tid >> 5;
    const int wrow = wid >> 1;
    const int wcol = wid & 1;
    const int g = lane >> 2, tg = lane & 3;

    float acc[2][8][4];
#pragma unroll
    for (int i = 0; i < 2; i++)
#pragma unroll
        for (int j = 0; j < 8; j++)
#pragma unroll
            for (int q = 0; q < 4; q++) acc[i][j][q] = 0.f;

    const uint2* BpW = Bp + (size_t)(wcol * 8) * 8 * 32 + lane;

#pragma unroll
    for (int kt = 0; kt < 8; kt++) {
        uint2 bf[8];
#pragma unroll
        for (int j = 0; j < 8; j++)
            bf[j] = BpW[(size_t)(j * 8 + kt) * 32];
        uint32_t af[2][4];
#pragma unroll
        for (int i = 0; i < 2; i++) {
            int r = wrow * 32 + i * 16 + g;
            int c = kt * 16 + tg * 2;
            af[i][0] = *(const uint32_t*)(smh + r * HPITCH + c);
            af[i][1] = *(const uint32_t*)(smh + (r + 8) * HPITCH + c);
            af[i][2] = *(const uint32_t*)(smh + r * HPITCH + c + 8);
            af[i][3] = *(const uint32_t*)(smh + (r + 8) * HPITCH + c + 8);
        }
#pragma unroll
        for (int i = 0; i < 2; i++)
#pragma unroll
            for (int j = 0; j < 8; j++)
                mma_f16(acc[i][j], af[i], (const uint32_t*)&bf[j]);
    }

#pragma unroll
    for (int i = 0; i < 2; i++) {
        int r = row0 + wrow * 32 + i * 16 + g;
#pragma unroll
        for (int j = 0; j < 8; j++) {
            int col = wcol * 64 + j * 8 + tg * 2;
            if (r < nrows)
                *(__half2*)(C + (size_t)r * 128 + col) =
                    __floats2half2_rn(acc[i][j][0], acc[i][j][1]);
            if (r + 8 < nrows)
                *(__half2*)(C + (size_t)(r + 8) * 128 + col) =
                    __floats2half2_rn(acc[i][j][2], acc[i][j][3]);
        }
    }
}

__global__ __launch_bounds__(256) void k_gemm_h(const __half* __restrict__ A,
                                                const uint2* __restrict__ Bp,
                                                __half* __restrict__ C, int nrows) {
    extern __shared__ __half smh[];                 // [128][136] fp16
    const int tid = threadIdx.x;
    const int row0 = blockIdx.x * 128;

#pragma unroll
    for (int i = 0; i < 8; i++) {
        int idx = i * 256 + tid;
        int r = idx >> 4;
        int c = idx & 15;
        uint4 v = make_uint4(0u, 0u, 0u, 0u);
        if (row0 + r < nrows)
            v = ((const uint4*)(A + (size_t)(row0 + r) * 128))[c];
        *(uint4*)(smh + r * HPITCH + c * 8) = v;
    }
    __syncthreads();
    gemm_body(smh, Bp, C, nrows, row0, tid);
}

// layer-1 variant: fp32 input, converts to fp16 while staging (replaces k_x2h)
__global__ __launch_bounds__(256) void k_gemm_f(const float* __restrict__ A,
                                                const uint2* __restrict__ Bp,
                                                __half* __restrict__ C, int nrows) {
    extern __shared__ __half smh[];
    const int tid = threadIdx.x;
    const int row0 = blockIdx.x * 128;

#pragma unroll
    for (int i = 0; i < 8; i++) {
        int idx = i * 256 + tid;
        int r = idx >> 4;
        int c = idx & 15;                            // 8 halves per slot
        uint4 o = make_uint4(0u, 0u, 0u, 0u);
        if (row0 + r < nrows) {
            const float4* src = (const float4*)(A + (size_t)(row0 + r) * 128) + c * 2;
            float4 v0 = src[0];
            float4 v1 = src[1];
            __half2 h0 = __floats2half2_rn(v0.x, v0.y);
            __half2 h1 = __floats2half2_rn(v0.z, v0.w);
            __half2 h2 = __floats2half2_rn(v1.x, v1.y);
            __half2 h3 = __floats2half2_rn(v1.z, v1.w);
            o.x = *(uint32_t*)&h0; o.y = *(uint32_t*)&h1;
            o.z = *(uint32_t*)&h2; o.w = *(uint32_t*)&h3;
        }
        *(uint4*)(smh + r * HPITCH + c * 8) = o;
    }
    __syncthreads();
    gemm_body(smh, Bp, C, nrows, row0, tid);
}

// ---------------- aggregation: FULL warp per node, uint2 lanes, 4-edge unroll ----------------
__device__ __forceinline__ void accum4(float4& A, uint2 r, float m) {
    float2 p0 = __half22float2(*(__half2*)&r.x);
    float2 p1 = __half22float2(*(__half2*)&r.y);
    A.x = fmaf(p0.x, m, A.x); A.y = fmaf(p0.y, m, A.y);
    A.z = fmaf(p1.x, m, A.z); A.w = fmaf(p1.y, m, A.w);
}

__global__ __launch_bounds__(256) void k_aggregate(const __half* __restrict__ H,
                                                   const float* __restrict__ bias,
                                                   __half* __restrict__ Hout,
                                                   float* __restrict__ Fout,
                                                   float* __restrict__ Fout2,
                                                   int n, int relu) {
    const int lane = threadIdx.x & 31;
    const int node = blockIdx.x * 8 + (threadIdx.x >> 5);
    if (node >= n) return;

    const uint2* H2 = (const uint2*)H;       // 32 uint2 per 128-half row

    float di = g_dinv[node];
    uint2 sr = __ldcg(H2 + (size_t)node * 32 + lane);
    float4 a0 = make_float4(0.f, 0.f, 0.f, 0.f), a1 = a0;
    accum4(a0, sr, di * di);

    int e = g_rowptr[node], e1 = g_rowptr[node + 1];
    for (; e + 3 < e1; e += 4) {
        int2 E0 = g_edge[e],     E1 = g_edge[e + 1];
        int2 E2 = g_edge[e + 2], E3 = g_edge[e + 3];
        uint2 r0 = __ldcg(H2 + (size_t)E0.x * 32 + lane);
        uint2 r1 = __ldcg(H2 + (size_t)E1.x * 32 + lane);
        uint2 r2 = __ldcg(H2 + (size_t)E2.x * 32 + lane);
        uint2 r3 = __ldcg(H2 + (size_t)E3.x * 32 + lane);
        accum4(a0, r0, __int_as_float(E0.y));
        accum4(a1, r1, __int_as_float(E1.y));
        accum4(a0, r2, __int_as_float(E2.y));
        accum4(a1, r3, __int_as_float(E3.y));
    }
    if (e + 1 < e1) {
        int2 E0 = g_edge[e], E1 = g_edge[e + 1];
        uint2 r0 = __ldcg(H2 + (size_t)E0.x * 32 + lane);
        uint2 r1 = __ldcg(H2 + (size_t)E1.x * 32 + lane);
        accum4(a0, r0, __int_as_float(E0.y));
        accum4(a1, r1, __int_as_float(E1.y));
        e += 2;
    }
    if (e < e1) {
        int2 E0 = g_edge[e];
        uint2 r0 = __ldcg(H2 + (size_t)E0.x * 32 + lane);
        accum4(a0, r0, __int_as_float(E0.y));
    }

    float4 bv = *(const float4*)(bias + lane * 4);
    float4 o = make_float4(a0.x + a1.x + bv.x, a0.y + a1.y + bv.y,
                           a0.z + a1.z + bv.z, a0.w + a1.w + bv.w);
    if (relu) {
        o.x = fmaxf(o.x, 0.f); o.y = fmaxf(o.y, 0.f);
        o.z = fmaxf(o.z, 0.f); o.w = fmaxf(o.w, 0.f);
    }
    if (Hout) {
        __half2 h0 = __floats2half2_rn(o.x, o.y);
        __half2 h1 = __floats2half2_rn(o.z, o.w);
        uint2 st;
        st.x = *(uint32_t*)&h0;
        st.y = *(uint32_t*)&h1;
        ((uint2*)(Hout + (size_t)node * 128))[lane] = st;
    } else {
        size_t off = (size_t)node * 128 + lane * 4;
        *(float4*)(Fout + off) = o;
        if (Fout2) *(float4*)(Fout2 + off) = o;
    }
}

// ---------------- launch ----------------
extern "C" void kernel_launch(void* const* d_in, const int* in_sizes, int n_in,
                              void* d_out, int out_size) {
    const float* x  = (const float*)d_in[0];
    const int*   ei = (const int*)d_in[1];
    const float* W1 = (const float*)d_in[2];
    const float* b1 = (const float*)d_in[3];
    const float* W2 = (const float*)d_in[4];
    const float* b2 = (const float*)d_in[5];
    const float* W3 = (const float*)d_in[6];
    const float* b3 = (const float*)d_in[7];

    int N = in_sizes[0] / FDIM;
    if (N > NN) N = NN;
    int E = in_sizes[1] / 2;
    if (E > EMAX) E = EMAX;

    static __half* t  = nullptr;
    static __half* xh = nullptr;
    static __half* hb = nullptr;
    static uint32_t* bp = nullptr;
    static cudaStream_t s2 = nullptr;
    static cudaEvent_t evF = nullptr, evJ = nullptr;
    static bool inited = false;
    if (!inited) {
        cudaGetSymbolAddress((void**)&t, g_t);
        cudaGetSymbolAddress((void**)&xh, g_xh);
        cudaGetSymbolAddress((void**)&hb, g_hb);
        cudaGetSymbolAddress((void**)&bp, g_Bp);
        cudaFuncSetAttribute(k_gemm_h, cudaFuncAttributeMaxDynamicSharedMemorySize,
                             SMEM_GEMM);
        cudaFuncSetAttribute(k_gemm_f, cudaFuncAttributeMaxDynamicSharedMemorySize,
                             SMEM_GEMM);
        cudaStreamCreateWithFlags(&s2, cudaStreamNonBlocking);
        cudaEventCreateWithFlags(&evF, cudaEventDisableTiming);
        cudaEventCreateWithFlags(&evJ, cudaEventDisableTiming);
        inited = true;
    }
    const uint2* Bp1 = (const uint2*)bp;
    const uint2* Bp2 = (const uint2*)(bp + 8192);
    const uint2* Bp3 = (const uint2*)(bp + 2 * 8192);

    const int nScan = (N + 1023) / 1024;
    const int T4 = (E + 3) / 4;                   // edges per ILP slot
    const int gE4 = (T4 + 255) / 256;
    const int gGemm = (N + 127) / 128;
    const int gAgg  = (N + 7) / 8;
    float* out = (float*)d_out;
    int half = N * FDIM;
    float* out2 = (out_size >= 2 * half) ? out + half : nullptr;

    // fork: CSR build on s2, concurrent with weight prep + layer-1 GEMM
    cudaEventRecord(evF, 0);
    cudaStreamWaitEvent(s2, evF, 0);
    k_count<<<gE4, 256, 0, s2>>>(ei, E, T4);
    k_scan<<<nScan, 1024, 0, s2>>>(N, E);
    k_scatter<<<gE4, 256, 0, s2>>>(ei, E, T4);
    cudaEventRecord(evJ, s2);

    k_bperm3<<<48, 256>>>(W1, W2, W3);
    k_gemm_f<<<gGemm, 256, SMEM_GEMM>>>(x, Bp1, t, N);   // fp32 in, converts inline

    // join: aggregation needs the CSR
    cudaStreamWaitEvent(0, evJ, 0);
    k_aggregate<<<gAgg, 256>>>(t, b1, hb, nullptr, nullptr, N, 1);
    k_gemm_h<<<gGemm, 256, SMEM_GEMM>>>(hb, Bp2, t, N);
    k_aggregate<<<gAgg, 256>>>(t, b2, xh, nullptr, nullptr, N, 1);
    k_gemm_h<<<gGemm, 256, SMEM_GEMM>>>(xh, Bp3, t, N);
    k_aggregate<<<gAgg, 256>>>(t, b3, nullptr, out, out2, N, 0);
}